// round 14
// baseline (speedup 1.0000x reference)
#include <cuda_runtime.h>
#include <cuda_bf16.h>
#include <cstdint>

#define NN 100000
#define EE 300000
#define FIN 128
#define HID 256
#define GG 2048
#define EPS 1e-5f

// ---------------- scratch ----------------
__device__ __align__(16) float g_bufA[(size_t)NN * HID];            // xw (fp32, gather source)
__device__ __align__(16) float g_h[(size_t)NN * HID];               // layer activations
__device__ __align__(16) __nv_bfloat16 g_wth[3 * HID * HID];        // W^T hi per layer [n][k]
__device__ __align__(16) __nv_bfloat16 g_wtl[3 * HID * HID];        // W^T lo per layer [n][k]
__device__ __align__(16) int   g_degi[NN];
__device__ __align__(16) float g_dinv[NN];
__device__ __align__(16) float g_dinv2[NN];
__device__ __align__(16) int   g_rowptr[NN + 1];
__device__ __align__(16) int   g_cursor[NN];
__device__ __align__(16) int   g_csrc[EE];
__device__ __align__(16) float g_ccoef[EE];
__device__ __align__(16) float g_stats[2 * HID];
__device__ __align__(16) float g_scale[HID];
__device__ __align__(16) float g_shift[HID];
__device__ __align__(16) float g_pooled[(size_t)GG * HID];
__device__ __align__(16) float g_hidden[(size_t)GG * HID];
__device__ __align__(16) int   g_src32[EE];
__device__ __align__(16) int   g_dst32[EE];
__device__ __align__(16) int   g_batch32[NN];
__device__ int g_anyOdd;

// ---------------- helpers ----------------
__device__ __forceinline__ uint32_t smem_u32(const void* p) {
    uint32_t a;
    asm("{ .reg .u64 t; cvta.to.shared.u64 t, %1; cvt.u32.u64 %0, t; }" : "=r"(a) : "l"(p));
    return a;
}
__device__ __forceinline__ void ldm_x4(uint32_t& a0, uint32_t& a1, uint32_t& a2, uint32_t& a3, uint32_t addr) {
    asm volatile("ldmatrix.sync.aligned.m8n8.x4.shared.b16 {%0,%1,%2,%3}, [%4];"
                 : "=r"(a0), "=r"(a1), "=r"(a2), "=r"(a3) : "r"(addr));
}
__device__ __forceinline__ void ldm_x2(uint32_t& b0, uint32_t& b1, uint32_t addr) {
    asm volatile("ldmatrix.sync.aligned.m8n8.x2.shared.b16 {%0,%1}, [%2];"
                 : "=r"(b0), "=r"(b1) : "r"(addr));
}
__device__ __forceinline__ void mma_16816(float* d, const uint32_t* a, const uint32_t* b) {
    asm volatile("mma.sync.aligned.m16n8k16.row.col.f32.bf16.bf16.f32 "
                 "{%0,%1,%2,%3}, {%4,%5,%6,%7}, {%8,%9}, {%0,%1,%2,%3};"
                 : "+f"(d[0]), "+f"(d[1]), "+f"(d[2]), "+f"(d[3])
                 : "r"(a[0]), "r"(a[1]), "r"(a[2]), "r"(a[3]), "r"(b[0]), "r"(b[1]));
}
__device__ __forceinline__ void cp16(uint32_t dst, const void* src) {
    asm volatile("cp.async.ca.shared.global [%0], [%1], 16;" :: "r"(dst), "l"(src));
}
__device__ __forceinline__ uint32_t pack_bf2(__nv_bfloat16 a, __nv_bfloat16 b) {
    __nv_bfloat162 t(a, b);
    return *(uint32_t*)&t;
}

// ---------------- index dtype detection ----------------
__global__ void det_init_kernel() { g_anyOdd = 0; }

__global__ void det_kernel(const unsigned int* __restrict__ raw, int cnt) {
    int i = blockIdx.x * blockDim.x + threadIdx.x;
    int odd = 2 * i + 1;
    if (odd < cnt && raw[odd] != 0u) g_anyOdd = 1;
}

// fused: convert src/dst/batch to int32 + accumulate integer degree
__global__ void conv_deg_kernel(const unsigned int* __restrict__ eiRaw,
                                const unsigned int* __restrict__ batchRaw,
                                int E, int N) {
    int i = blockIdx.x * blockDim.x + threadIdx.x;
    int is32 = g_anyOdd;
    if (i < E) {
        int s = (int)(is32 ? eiRaw[i] : eiRaw[2 * (size_t)i]);
        int d = (int)(is32 ? eiRaw[(size_t)E + i] : eiRaw[2 * (size_t)E + 2 * (size_t)i]);
        g_src32[i] = s;
        g_dst32[i] = d;
        if (d >= 0 && d < N) atomicAdd(&g_degi[d], 1);
    }
    if (i < N) {
        g_batch32[i] = (int)(is32 ? batchRaw[i] : batchRaw[2 * (size_t)i]);
    }
}

// ---------------- zero fill (sel: 0=degi, 1=stats, 2=pooled) ----------------
__global__ void zero_kernel(int sel, int n) {
    int i = blockIdx.x * blockDim.x + threadIdx.x;
    if (i >= n) return;
    if (sel == 0) g_degi[i] = 0;
    else if (sel == 1) g_stats[i] = 0.0f;
    else g_pooled[i] = 0.0f;
}

__global__ void dinv_kernel(int N) {
    int i = blockIdx.x * blockDim.x + threadIdx.x;
    if (i < N) {
        float d = (float)g_degi[i] + 1.0f;
        g_dinv[i]  = rsqrtf(d);
        g_dinv2[i] = 1.0f / d;
    }
}

// single-block exclusive scan of g_degi -> g_rowptr / g_cursor
__global__ void __launch_bounds__(1024) scan_kernel(int N) {
    __shared__ int partial[1024];
    int tid = threadIdx.x;
    int per = (N + 1023) / 1024;
    int start = tid * per;
    int end = min(start + per, N);
    int sum = 0;
    for (int i = start; i < end; i++) sum += g_degi[i];
    partial[tid] = sum;
    __syncthreads();
    for (int off = 1; off < 1024; off <<= 1) {
        int v = (tid >= off) ? partial[tid - off] : 0;
        __syncthreads();
        if (tid >= off) partial[tid] += v;
        __syncthreads();
    }
    int run = (tid == 0) ? 0 : partial[tid - 1];
    for (int i = start; i < end; i++) {
        g_rowptr[i] = run;
        g_cursor[i] = run;
        run += g_degi[i];
    }
    if (tid == 0) g_rowptr[N] = partial[1023];
}

// fused: coeff compute + CSR fill
__global__ void coeff_csr_kernel(int E) {
    int i = blockIdx.x * blockDim.x + threadIdx.x;
    if (i >= E) return;
    int s = g_src32[i];
    int d = g_dst32[i];
    float c = g_dinv[s] * g_dinv[d];
    int p = atomicAdd(&g_cursor[d], 1);
    g_csrc[p] = s;
    g_ccoef[p] = c;
}

// ---------------- W[K,HID] -> Wt[HID,K] hi/lo ----------------
__global__ void wt_kernel(const float* __restrict__ W, int layer, int K) {
    int i = blockIdx.x * blockDim.x + threadIdx.x;
    if (i >= K * HID) return;
    int n = i / K, k = i % K;
    float v = W[(size_t)k * HID + n];
    __nv_bfloat16 h = __float2bfloat16(v);
    size_t o = (size_t)layer * HID * HID + (size_t)n * K + k;
    g_wth[o] = h;
    g_wtl[o] = __float2bfloat16(v - __bfloat162float(h));
}

// ---------------- pipelined HMMA GEMM with fused BN-on-load ----------------
// inSel: 0 = Aext (x), 1 = g_h (+BN via g_scale/g_shift global reads).
#define ASTRIDE 40
#define STG 10240
#define OFF_AH 0
#define OFF_AL (2 * STG)
#define OFF_BH (4 * STG)
#define OFF_BL (6 * STG)
#define GEMM_SMEM (8 * STG)   // 81920

__global__ void __launch_bounds__(256, 2)
gemm_mma_kernel(int layer, int K, int M, const float* __restrict__ Aext,
                int inSel) {
    extern __shared__ __align__(16) char smem[];
    uint32_t sb = smem_u32(smem);

    int tid = threadIdx.x;
    int warp = tid >> 5, lane = tid & 31;
    int mw = warp & 1;
    int nw = warp >> 1;
    int tileM = blockIdx.x * 128;
    int colBase = blockIdx.y * 128;
    int applyBn = (inSel != 0);

    const float* A = (inSel == 0) ? Aext : (const float*)g_h;
    const __nv_bfloat16* Wth = g_wth + (size_t)layer * HID * HID + (size_t)colBase * K;
    const __nv_bfloat16* Wtl = g_wtl + (size_t)layer * HID * HID + (size_t)colBase * K;

    float acc[4][4][4];
    #pragma unroll
    for (int i = 0; i < 4; i++)
        #pragma unroll
        for (int j = 0; j < 4; j++)
            #pragma unroll
            for (int v = 0; v < 4; v++) acc[i][j][v] = 0.f;

    int nChunks = K >> 5;
    float4 aReg[4];

    auto loadA = [&](int kt) {
        #pragma unroll
        for (int it = 0; it < 4; it++) {
            int idx = tid + it * 256;
            int row = idx >> 3, seg = idx & 7;
            float4 v = make_float4(0.f, 0.f, 0.f, 0.f);
            int gr = tileM + row;
            if (gr < M)
                v = *(const float4*)(A + (size_t)gr * K + kt + seg * 4);
            if (applyBn) {
                int col = kt + seg * 4;
                float4 sc = *(const float4*)(g_scale + col);
                float4 sh = *(const float4*)(g_shift + col);
                v.x = fmaxf(fmaf(v.x, sc.x, sh.x), 0.f);
                v.y = fmaxf(fmaf(v.y, sc.y, sh.y), 0.f);
                v.z = fmaxf(fmaf(v.z, sc.z, sh.z), 0.f);
                v.w = fmaxf(fmaf(v.w, sc.w, sh.w), 0.f);
            }
            aReg[it] = v;
        }
    };
    auto storeA = [&](int stage) {
        uint32_t baseH = sb + OFF_AH + stage * STG;
        uint32_t baseL = sb + OFF_AL + stage * STG;
        #pragma unroll
        for (int it = 0; it < 4; it++) {
            int idx = tid + it * 256;
            int row = idx >> 3, seg = idx & 7;
            float4 v = aReg[it];
            __nv_bfloat16 hx = __float2bfloat16(v.x), hy = __float2bfloat16(v.y);
            __nv_bfloat16 hz = __float2bfloat16(v.z), hw = __float2bfloat16(v.w);
            uint32_t off = (uint32_t)(row * 80 + seg * 8);
            uint2 ph = make_uint2(pack_bf2(hx, hy), pack_bf2(hz, hw));
            uint2 pl = make_uint2(
                pack_bf2(__float2bfloat16(v.x - __bfloat162float(hx)),
                         __float2bfloat16(v.y - __bfloat162float(hy))),
                pack_bf2(__float2bfloat16(v.z - __bfloat162float(hz)),
                         __float2bfloat16(v.w - __bfloat162float(hw))));
            asm volatile("st.shared.v2.b32 [%0], {%1,%2};" :: "r"(baseH + off), "r"(ph.x), "r"(ph.y));
            asm volatile("st.shared.v2.b32 [%0], {%1,%2};" :: "r"(baseL + off), "r"(pl.x), "r"(pl.y));
        }
    };
    auto loadB = [&](int kt, int stage) {
        uint32_t baseH = sb + OFF_BH + stage * STG;
        uint32_t baseL = sb + OFF_BL + stage * STG;
        #pragma unroll
        for (int it = 0; it < 2; it++) {
            int idx = tid + it * 256;
            int row = idx >> 2, seg = idx & 3;
            uint32_t off = (uint32_t)(row * 80 + seg * 16);
            size_t go = (size_t)row * K + kt + seg * 8;
            cp16(baseH + off, Wth + go);
            cp16(baseL + off, Wtl + go);
        }
        asm volatile("cp.async.commit_group;");
    };
    auto compute = [&](int stage) {
        uint32_t aH = sb + OFF_AH + stage * STG, aL = sb + OFF_AL + stage * STG;
        uint32_t bH = sb + OFF_BH + stage * STG, bL = sb + OFF_BL + stage * STG;
        #pragma unroll
        for (int ks = 0; ks < 2; ks++) {
            uint32_t bh[4][2], bl[4][2];
            int brow = nw * 32 + (lane & 7);
            int bcol = ks * 32 + ((lane >> 3) & 1) * 16;
            #pragma unroll
            for (int j = 0; j < 4; j++) {
                uint32_t off = (uint32_t)((brow + j * 8) * 80 + bcol);
                ldm_x2(bh[j][0], bh[j][1], bH + off);
                ldm_x2(bl[j][0], bl[j][1], bL + off);
            }
            int arow = mw * 64 + (lane & 15);
            int acol = ks * 32 + (lane >> 4) * 16;
            #pragma unroll
            for (int i = 0; i < 4; i++) {
                uint32_t off = (uint32_t)((arow + i * 16) * 80 + acol);
                uint32_t ah[4], al[4];
                ldm_x4(ah[0], ah[1], ah[2], ah[3], aH + off);
                ldm_x4(al[0], al[1], al[2], al[3], aL + off);
                #pragma unroll
                for (int j = 0; j < 4; j++) {
                    mma_16816(acc[i][j], ah, bh[j]);
                    mma_16816(acc[i][j], ah, bl[j]);
                    mma_16816(acc[i][j], al, bh[j]);
                }
            }
        }
    };

    loadA(0);
    loadB(0, 0);
    storeA(0);
    asm volatile("cp.async.wait_group 0;");
    __syncthreads();

    for (int c = 0; c < nChunks; c++) {
        int cur = c & 1, nxt = cur ^ 1;
        bool hasNext = (c + 1 < nChunks);
        if (hasNext) {
            loadA((c + 1) << 5);
            loadB((c + 1) << 5, nxt);
        }
        compute(cur);
        if (hasNext) {
            storeA(nxt);
            asm volatile("cp.async.wait_group 0;");
        }
        __syncthreads();
    }

    // epilogue: write xw (bufA)
    int groupRow = lane >> 2;
    int colOff = colBase + nw * 32 + (lane & 3) * 2;
    #pragma unroll
    for (int i = 0; i < 4; i++) {
        int r0 = tileM + mw * 64 + i * 16 + groupRow;
        #pragma unroll
        for (int half = 0; half < 2; half++) {
            int row = r0 + half * 8;
            if (row >= M) continue;
            #pragma unroll
            for (int j = 0; j < 4; j++) {
                int col = colOff + j * 8;
                size_t o = (size_t)row * HID + col;
                *(float2*)(g_bufA + o) =
                    make_float2(acc[i][j][half * 2 + 0], acc[i][j][half * 2 + 1]);
            }
        }
    }
}

// ---------------- CSR gather aggregation + fused BN stats ----------------
// block = 256 threads = 8 warps; warp w handles 8 nodes as 4 PAIRS processed with two
// concurrent gather streams (doubles memory-level parallelism per warp vs R13).
// Each thread covers 8 features (two float4 halves). 1563 blocks.
#define AGG_NPB 64        // nodes per block (8 warps x 8)
#define AGG_NPW 8         // nodes per warp
__global__ void __launch_bounds__(256) agg_kernel(int N, const float* __restrict__ bias) {
    __shared__ float red[2][8][HID];   // 16 KB
    int tid = threadIdx.x;
    int w = tid >> 5;          // 0..7
    int lane = tid & 31;
    int f0 = lane * 4;
    int f1 = 128 + lane * 4;
    float4 b0 = *(const float4*)(bias + f0);
    float4 b1 = *(const float4*)(bias + f1);
    float4 s0 = make_float4(0.f, 0.f, 0.f, 0.f), s1 = s0;
    float4 q0 = s0, q1 = s0;

    int base = blockIdx.x * AGG_NPB + w * AGG_NPW;
    int nEnd = min(base + AGG_NPW, N);

    #pragma unroll
    for (int p = 0; p < 4; p++) {
        int nA = base + p * 2;
        int nB = nA + 1;
        bool vA = nA < nEnd;
        bool vB = nB < nEnd;
        if (!vA) break;

        // stream A accumulators
        float d2A = g_dinv2[nA];
        const float* rowA = g_bufA + (size_t)nA * HID;
        float4 vA0 = *(const float4*)(rowA + f0);
        float4 vA1 = *(const float4*)(rowA + f1);
        float4 aA0, aA1;
        aA0.x = fmaf(vA0.x, d2A, b0.x); aA0.y = fmaf(vA0.y, d2A, b0.y);
        aA0.z = fmaf(vA0.z, d2A, b0.z); aA0.w = fmaf(vA0.w, d2A, b0.w);
        aA1.x = fmaf(vA1.x, d2A, b1.x); aA1.y = fmaf(vA1.y, d2A, b1.y);
        aA1.z = fmaf(vA1.z, d2A, b1.z); aA1.w = fmaf(vA1.w, d2A, b1.w);

        // stream B accumulators
        float4 aB0 = make_float4(0.f, 0.f, 0.f, 0.f), aB1 = aB0;
        int eB = 0, eB1 = 0;
        if (vB) {
            float d2B = g_dinv2[nB];
            const float* rowB = g_bufA + (size_t)nB * HID;
            float4 vB0 = *(const float4*)(rowB + f0);
            float4 vB1 = *(const float4*)(rowB + f1);
            aB0.x = fmaf(vB0.x, d2B, b0.x); aB0.y = fmaf(vB0.y, d2B, b0.y);
            aB0.z = fmaf(vB0.z, d2B, b0.z); aB0.w = fmaf(vB0.w, d2B, b0.w);
            aB1.x = fmaf(vB1.x, d2B, b1.x); aB1.y = fmaf(vB1.y, d2B, b1.y);
            aB1.z = fmaf(vB1.z, d2B, b1.z); aB1.w = fmaf(vB1.w, d2B, b1.w);
            eB = g_rowptr[nB]; eB1 = g_rowptr[nB + 1];
        }
        int eA = g_rowptr[nA], eA1 = g_rowptr[nA + 1];

        // interleaved edge walk: two independent dependent-load chains in flight
        while (eA < eA1 || eB < eB1) {
            int srcA = 0, srcB = 0;
            float cA = 0.f, cB = 0.f;
            bool dA = eA < eA1, dB = eB < eB1;
            if (dA) { srcA = g_csrc[eA]; cA = g_ccoef[eA]; }
            if (dB) { srcB = g_csrc[eB]; cB = g_ccoef[eB]; }
            if (dA) {
                const float* sr = g_bufA + (size_t)srcA * HID;
                float4 w0 = *(const float4*)(sr + f0);
                float4 w1 = *(const float4*)(sr + f1);
                aA0.x = fmaf(w0.x, cA, aA0.x); aA0.y = fmaf(w0.y, cA, aA0.y);
                aA0.z = fmaf(w0.z, cA, aA0.z); aA0.w = fmaf(w0.w, cA, aA0.w);
                aA1.x = fmaf(w1.x, cA, aA1.x); aA1.y = fmaf(w1.y, cA, aA1.y);
                aA1.z = fmaf(w1.z, cA, aA1.z); aA1.w = fmaf(w1.w, cA, aA1.w);
                eA++;
            }
            if (dB) {
                const float* sr = g_bufA + (size_t)srcB * HID;
                float4 w0 = *(const float4*)(sr + f0);
                float4 w1 = *(const float4*)(sr + f1);
                aB0.x = fmaf(w0.x, cB, aB0.x); aB0.y = fmaf(w0.y, cB, aB0.y);
                aB0.z = fmaf(w0.z, cB, aB0.z); aB0.w = fmaf(w0.w, cB, aB0.w);
                aB1.x = fmaf(w1.x, cB, aB1.x); aB1.y = fmaf(w1.y, cB, aB1.y);
                aB1.z = fmaf(w1.z, cB, aB1.z); aB1.w = fmaf(w1.w, cB, aB1.w);
                eB++;
            }
        }

        // write + stats stream A
        float* oA = g_h + (size_t)nA * HID;
        *(float4*)(oA + f0) = aA0;
        *(float4*)(oA + f1) = aA1;
        s0.x += aA0.x; s0.y += aA0.y; s0.z += aA0.z; s0.w += aA0.w;
        s1.x += aA1.x; s1.y += aA1.y; s1.z += aA1.z; s1.w += aA1.w;
        q0.x = fmaf(aA0.x, aA0.x, q0.x); q0.y = fmaf(aA0.y, aA0.y, q0.y);
        q0.z = fmaf(aA0.z, aA0.z, q0.z); q0.w = fmaf(aA0.w, aA0.w, q0.w);
        q1.x = fmaf(aA1.x, aA1.x, q1.x); q1.y = fmaf(aA1.y, aA1.y, q1.y);
        q1.z = fmaf(aA1.z, aA1.z, q1.z); q1.w = fmaf(aA1.w, aA1.w, q1.w);

        if (vB) {
            float* oB = g_h + (size_t)nB * HID;
            *(float4*)(oB + f0) = aB0;
            *(float4*)(oB + f1) = aB1;
            s0.x += aB0.x; s0.y += aB0.y; s0.z += aB0.z; s0.w += aB0.w;
            s1.x += aB1.x; s1.y += aB1.y; s1.z += aB1.z; s1.w += aB1.w;
            q0.x = fmaf(aB0.x, aB0.x, q0.x); q0.y = fmaf(aB0.y, aB0.y, q0.y);
            q0.z = fmaf(aB0.z, aB0.z, q0.z); q0.w = fmaf(aB0.w, aB0.w, q0.w);
            q1.x = fmaf(aB1.x, aB1.x, q1.x); q1.y = fmaf(aB1.y, aB1.y, q1.y);
            q1.z = fmaf(aB1.z, aB1.z, q1.z); q1.w = fmaf(aB1.w, aB1.w, q1.w);
        }
    }

    *(float4*)(&red[0][w][f0]) = s0;
    *(float4*)(&red[0][w][f1]) = s1;
    *(float4*)(&red[1][w][f0]) = q0;
    *(float4*)(&red[1][w][f1]) = q1;
    __syncthreads();
    if (w == 0) {
        #pragma unroll
        for (int half = 0; half < 2; half++) {
            int fb = (half == 0) ? f0 : f1;
            #pragma unroll
            for (int k = 0; k < 4; k++) {
                int ff = fb + k;
                float ts = 0.f, tq = 0.f;
                #pragma unroll
                for (int g = 0; g < 8; g++) {
                    ts += red[0][g][ff];
                    tq += red[1][g][ff];
                }
                atomicAdd(&g_stats[ff], ts);
                atomicAdd(&g_stats[HID + ff], tq);
            }
        }
    }
}

// bn finalize + reset stats for the next layer (single block, no race)
__global__ void bn_final_kernel(const float* __restrict__ gamma,
                                const float* __restrict__ beta, int N) {
    int f = threadIdx.x;
    float invN = 1.0f / (float)N;
    float mean = g_stats[f] * invN;
    float var  = g_stats[HID + f] * invN - mean * mean;
    float sc = gamma[f] * rsqrtf(var + EPS);
    g_scale[f] = sc;
    g_shift[f] = beta[f] - mean * sc;
    g_stats[f] = 0.0f;
    g_stats[HID + f] = 0.0f;
}

// ---------------- pooling: run-length accumulation + fused BN3 + ReLU ----------------
#define PNPB 64
__global__ void __launch_bounds__(256) pool_kernel(int N) {
    int f = threadIdx.x;
    int n0 = blockIdx.x * PNPB;
    int n1 = min(n0 + PNPB, N);
    if (n0 >= N) return;
    float sc = g_scale[f], sh = g_shift[f];
    float acc = 0.f;
    int curG = g_batch32[n0];
    for (int n = n0; n < n1; n++) {
        int g = g_batch32[n];
        if (g != curG) {
            atomicAdd(&g_pooled[(size_t)curG * HID + f], acc);
            acc = 0.f;
            curG = g;
        }
        float v = g_h[(size_t)n * HID + f];
        acc += fmaxf(fmaf(v, sc, sh), 0.f);
    }
    atomicAdd(&g_pooled[(size_t)curG * HID + f], acc);
}

// ---------------- MLP head fp32 GEMM ----------------
__global__ __launch_bounds__(256) void head_gemm_kernel(
    const float* __restrict__ B, const float* __restrict__ bias, int M, int K) {
    const float* A = (const float*)g_pooled;
    float* C = g_hidden;
    const int Ncols = HID;

    __shared__ float As[16][64];
    __shared__ float Bs[16][64];
    int tid = threadIdx.x;
    int ty = tid >> 4;
    int tx = tid & 15;
    int rowBase = blockIdx.x * 64;
    int colBase = blockIdx.y * 64;

    float acc[4][4] = {};
    int lr = tid >> 2;
    int lc = tid & 3;
    int br = tid >> 4;
    int bc = tid & 15;

    for (int kt = 0; kt < K; kt += 16) {
        float4 av = make_float4(0.f, 0.f, 0.f, 0.f);
        int arow = rowBase + lr;
        if (arow < M)
            av = *(const float4*)(A + (size_t)arow * K + kt + lc * 4);
        As[lc * 4 + 0][lr] = av.x;
        As[lc * 4 + 1][lr] = av.y;
        As[lc * 4 + 2][lr] = av.z;
        As[lc * 4 + 3][lr] = av.w;
        float4 bv = *(const float4*)(B + (size_t)(kt + br) * Ncols + colBase + bc * 4);
        *(float4*)(&Bs[br][bc * 4]) = bv;
        __syncthreads();
        #pragma unroll
        for (int k = 0; k < 16; k++) {
            float ar[4], brv[4];
            #pragma unroll
            for (int i = 0; i < 4; i++) ar[i]  = As[k][ty * 4 + i];
            #pragma unroll
            for (int j = 0; j < 4; j++) brv[j] = Bs[k][tx * 4 + j];
            #pragma unroll
            for (int i = 0; i < 4; i++)
                #pragma unroll
                for (int j = 0; j < 4; j++)
                    acc[i][j] = fmaf(ar[i], brv[j], acc[i][j]);
        }
        __syncthreads();
    }
    #pragma unroll
    for (int i = 0; i < 4; i++) {
        int row = rowBase + ty * 4 + i;
        if (row >= M) continue;
        int col = colBase + tx * 4;
        float4 v;
        float* vp = &v.x;
        #pragma unroll
        for (int j = 0; j < 4; j++) {
            float t = acc[i][j] + bias[col + j];
            vp[j] = fmaxf(t, 0.f);
        }
        *(float4*)(C + (size_t)row * Ncols + col) = v;
    }
}

// ---------------- final dot ----------------
__global__ void final_dot_kernel(const float* __restrict__ LW2,
                                 const float* __restrict__ Lb2,
                                 float* __restrict__ out, int G) {
    int warp = (blockIdx.x * blockDim.x + threadIdx.x) >> 5;
    int lane = threadIdx.x & 31;
    if (warp >= G) return;
    const float* hrow = g_hidden + (size_t)warp * HID;
    float s = 0.f;
    #pragma unroll
    for (int i = 0; i < 8; i++)
        s = fmaf(hrow[lane + 32 * i], LW2[lane + 32 * i], s);
    #pragma unroll
    for (int o = 16; o; o >>= 1) s += __shfl_down_sync(0xffffffffu, s, o);
    if (lane == 0) out[warp] = s + Lb2[0];
}

// ---------------- host: launches ONLY ----------------
extern "C" void kernel_launch(void* const* d_in, const int* in_sizes, int n_in,
                              void* d_out, int out_size) {
    const float* x = (const float*)d_in[0];
    const unsigned int* eiRaw    = (const unsigned int*)d_in[1];
    const unsigned int* batchRaw = (const unsigned int*)d_in[2];
    const float* W1  = (const float*)d_in[3];
    const float* b1  = (const float*)d_in[4];
    const float* W2  = (const float*)d_in[5];
    const float* b2  = (const float*)d_in[6];
    const float* W3  = (const float*)d_in[7];
    const float* b3  = (const float*)d_in[8];
    const float* g1  = (const float*)d_in[9];
    const float* be1 = (const float*)d_in[10];
    const float* g2  = (const float*)d_in[11];
    const float* be2 = (const float*)d_in[12];
    const float* g3  = (const float*)d_in[13];
    const float* be3 = (const float*)d_in[14];
    const float* LW1 = (const float*)d_in[15];
    const float* Lb1 = (const float*)d_in[16];
    const float* LW2 = (const float*)d_in[17];
    const float* Lb2 = (const float*)d_in[18];
    float* out = (float*)d_out;

    const int N = in_sizes[0] / FIN;
    const int E = in_sizes[1] / 2;
    const int G = out_size;

    cudaFuncSetAttribute(gemm_mma_kernel, cudaFuncAttributeMaxDynamicSharedMemorySize, GEMM_SMEM);

    dim3 ggrid((N + 127) / 128, HID / 128);

    // launches 1-3: weight transpose + bf16 split
    wt_kernel<<<(FIN * HID + 255) / 256, 256>>>(W1, 0, FIN);
    wt_kernel<<<(HID * HID + 255) / 256, 256>>>(W2, 1, HID);
    wt_kernel<<<(HID * HID + 255) / 256, 256>>>(W3, 2, HID);
    // launch 4: layer-1 GEMM -- ncu captures the 4th launch
    gemm_mma_kernel<<<ggrid, 256, GEMM_SMEM>>>(0, FIN, N, x, 0);
    // prep
    zero_kernel<<<(N + 255) / 256, 256>>>(0, N);
    det_init_kernel<<<1, 1>>>();
    det_kernel<<<(E + 255) / 256, 256>>>(eiRaw, 2 * E);
    conv_deg_kernel<<<(E + 255) / 256, 256>>>(eiRaw, batchRaw, E, N);
    dinv_kernel<<<(N + 255) / 256, 256>>>(N);
    scan_kernel<<<1, 1024>>>(N);
    coeff_csr_kernel<<<(E + 255) / 256, 256>>>(E);
    zero_kernel<<<2, 256>>>(1, 2 * HID);

    // layer 1 tail
    agg_kernel<<<(N + AGG_NPB - 1) / AGG_NPB, 256>>>(N, b1);
    bn_final_kernel<<<1, HID>>>(g1, be1, N);
    // layer 2
    gemm_mma_kernel<<<ggrid, 256, GEMM_SMEM>>>(1, HID, N, nullptr, 1);
    agg_kernel<<<(N + AGG_NPB - 1) / AGG_NPB, 256>>>(N, b2);
    bn_final_kernel<<<1, HID>>>(g2, be2, N);
    // layer 3
    gemm_mma_kernel<<<ggrid, 256, GEMM_SMEM>>>(2, HID, N, nullptr, 1);
    agg_kernel<<<(N + AGG_NPB - 1) / AGG_NPB, 256>>>(N, b3);
    bn_final_kernel<<<1, HID>>>(g3, be3, N);

    // global add pool (BN3 + ReLU fused, run-length accumulation)
    zero_kernel<<<(G * HID + 255) / 256, 256>>>(2, G * HID);
    pool_kernel<<<(N + PNPB - 1) / PNPB, 256>>>(N);

    // MLP head
    dim3 mgrid((G + 63) / 64, HID / 64);
    head_gemm_kernel<<<mgrid, 256>>>(LW1, Lb1, G, HID);
    final_dot_kernel<<<(G * 32 + 255) / 256, 256>>>(LW2, Lb2, out, G);
}

// round 15
// speedup vs baseline: 1.0359x; 1.0359x over previous
#include <cuda_runtime.h>
#include <cuda_bf16.h>
#include <cstdint>

#define NN 100000
#define EE 300000
#define FIN 128
#define HID 256
#define GG 2048
#define EPS 1e-5f

// ---------------- scratch ----------------
__device__ __align__(16) float g_bufA[(size_t)NN * HID];            // agg output (GEMM input)
__device__ __align__(16) float g_h[(size_t)NN * HID];               // GEMM output (pre-BN h)
__device__ __align__(16) __nv_bfloat16 g_wth[3 * HID * HID];        // W^T hi per layer [n][k]
__device__ __align__(16) __nv_bfloat16 g_wtl[3 * HID * HID];        // W^T lo per layer [n][k]
__device__ __align__(16) int   g_degi[NN];
__device__ __align__(16) float g_dinv[NN];
__device__ __align__(16) float g_dinv2[NN];
__device__ __align__(16) int   g_rowptr[NN + 1];
__device__ __align__(16) int   g_cursor[NN];
__device__ __align__(16) int   g_csrc[EE];
__device__ __align__(16) float g_ccoef[EE];
__device__ __align__(16) float g_stats[2 * HID];
__device__ __align__(16) float g_scale[HID];
__device__ __align__(16) float g_shift[HID];
__device__ __align__(16) float g_pooled[(size_t)GG * HID];
__device__ __align__(16) float g_hidden[(size_t)GG * HID];
__device__ __align__(16) int   g_src32[EE];
__device__ __align__(16) int   g_dst32[EE];
__device__ __align__(16) int   g_batch32[NN];
__device__ int g_anyOdd;

// ---------------- helpers ----------------
__device__ __forceinline__ uint32_t smem_u32(const void* p) {
    uint32_t a;
    asm("{ .reg .u64 t; cvta.to.shared.u64 t, %1; cvt.u32.u64 %0, t; }" : "=r"(a) : "l"(p));
    return a;
}
__device__ __forceinline__ void ldm_x4(uint32_t& a0, uint32_t& a1, uint32_t& a2, uint32_t& a3, uint32_t addr) {
    asm volatile("ldmatrix.sync.aligned.m8n8.x4.shared.b16 {%0,%1,%2,%3}, [%4];"
                 : "=r"(a0), "=r"(a1), "=r"(a2), "=r"(a3) : "r"(addr));
}
__device__ __forceinline__ void ldm_x2(uint32_t& b0, uint32_t& b1, uint32_t addr) {
    asm volatile("ldmatrix.sync.aligned.m8n8.x2.shared.b16 {%0,%1}, [%2];"
                 : "=r"(b0), "=r"(b1) : "r"(addr));
}
__device__ __forceinline__ void mma_16816(float* d, const uint32_t* a, const uint32_t* b) {
    asm volatile("mma.sync.aligned.m16n8k16.row.col.f32.bf16.bf16.f32 "
                 "{%0,%1,%2,%3}, {%4,%5,%6,%7}, {%8,%9}, {%0,%1,%2,%3};"
                 : "+f"(d[0]), "+f"(d[1]), "+f"(d[2]), "+f"(d[3])
                 : "r"(a[0]), "r"(a[1]), "r"(a[2]), "r"(a[3]), "r"(b[0]), "r"(b[1]));
}
__device__ __forceinline__ void cp16(uint32_t dst, const void* src) {
    asm volatile("cp.async.ca.shared.global [%0], [%1], 16;" :: "r"(dst), "l"(src));
}
__device__ __forceinline__ uint32_t pack_bf2(__nv_bfloat16 a, __nv_bfloat16 b) {
    __nv_bfloat162 t(a, b);
    return *(uint32_t*)&t;
}

// ---------------- index dtype detection ----------------
__global__ void det_kernel(const unsigned int* __restrict__ raw, int cnt) {
    int i = blockIdx.x * blockDim.x + threadIdx.x;
    int odd = 2 * i + 1;
    if (odd < cnt && raw[odd] != 0u) g_anyOdd = 1;
}

// fused: convert src/dst/batch to int32 + accumulate integer degree
__global__ void conv_deg_kernel(const unsigned int* __restrict__ eiRaw,
                                const unsigned int* __restrict__ batchRaw,
                                int E, int N) {
    int i = blockIdx.x * blockDim.x + threadIdx.x;
    int is32 = g_anyOdd;
    if (i < E) {
        int s = (int)(is32 ? eiRaw[i] : eiRaw[2 * (size_t)i]);
        int d = (int)(is32 ? eiRaw[(size_t)E + i] : eiRaw[2 * (size_t)E + 2 * (size_t)i]);
        g_src32[i] = s;
        g_dst32[i] = d;
        if (d >= 0 && d < N) atomicAdd(&g_degi[d], 1);
    }
    if (i < N) {
        g_batch32[i] = (int)(is32 ? batchRaw[i] : batchRaw[2 * (size_t)i]);
    }
}

// ---------------- zero fill (sel: 0=degi+flag, 1=stats, 2=pooled) ----------------
__global__ void zero_kernel(int sel, int n) {
    int i = blockIdx.x * blockDim.x + threadIdx.x;
    if (i >= n) return;
    if (sel == 0) {
        g_degi[i] = 0;
        if (i == 0) g_anyOdd = 0;
    } else if (sel == 1) g_stats[i] = 0.0f;
    else g_pooled[i] = 0.0f;
}

__global__ void dinv_kernel(int N) {
    int i = blockIdx.x * blockDim.x + threadIdx.x;
    if (i < N) {
        float d = (float)g_degi[i] + 1.0f;
        g_dinv[i]  = rsqrtf(d);
        g_dinv2[i] = 1.0f / d;
    }
}

// single-block exclusive scan of g_degi -> g_rowptr / g_cursor
__global__ void __launch_bounds__(1024) scan_kernel(int N) {
    __shared__ int partial[1024];
    int tid = threadIdx.x;
    int per = (N + 1023) / 1024;
    int start = tid * per;
    int end = min(start + per, N);
    int sum = 0;
    for (int i = start; i < end; i++) sum += g_degi[i];
    partial[tid] = sum;
    __syncthreads();
    for (int off = 1; off < 1024; off <<= 1) {
        int v = (tid >= off) ? partial[tid - off] : 0;
        __syncthreads();
        if (tid >= off) partial[tid] += v;
        __syncthreads();
    }
    int run = (tid == 0) ? 0 : partial[tid - 1];
    for (int i = start; i < end; i++) {
        g_rowptr[i] = run;
        g_cursor[i] = run;
        run += g_degi[i];
    }
    if (tid == 0) g_rowptr[N] = partial[1023];
}

// fused: coeff compute + CSR fill
__global__ void coeff_csr_kernel(int E) {
    int i = blockIdx.x * blockDim.x + threadIdx.x;
    if (i >= E) return;
    int s = g_src32[i];
    int d = g_dst32[i];
    float c = g_dinv[s] * g_dinv[d];
    int p = atomicAdd(&g_cursor[d], 1);
    g_csrc[p] = s;
    g_ccoef[p] = c;
}

// ---------------- W[K,HID] -> Wt[HID,K] hi/lo ----------------
__global__ void wt_kernel(const float* __restrict__ W, int layer, int K) {
    int i = blockIdx.x * blockDim.x + threadIdx.x;
    if (i >= K * HID) return;
    int n = i / K, k = i % K;
    float v = W[(size_t)k * HID + n];
    __nv_bfloat16 h = __float2bfloat16(v);
    size_t o = (size_t)layer * HID * HID + (size_t)n * K + k;
    g_wth[o] = h;
    g_wtl[o] = __float2bfloat16(v - __bfloat162float(h));
}

// ---------------- CSR gather aggregation (BEFORE GEMM, on activations) ----------------
// a[n] = dinv2[n]*act(n) + sum_e c_e * act(src_e), act = applyBn ? relu(v*scale+shift) : v
// K = 128 (layer1 x) or 256 (layers 2-3 h). 8 warps x 8 serial nodes, thread covers
// 4 features (K=128) or 8 features (K=256). No stats, no bias -> lean + high occupancy.
#define AGG_NPB 64
#define AGG_NPW 8
__global__ void __launch_bounds__(256) agg_kernel(int N, int K,
                                                  const float* __restrict__ X, int applyBn) {
    int tid = threadIdx.x;
    int w = tid >> 5, lane = tid & 31;
    int f0 = lane * 4;
    int f1 = 128 + lane * 4;
    bool wide = (K == 256);
    const float* S = applyBn ? (const float*)g_h : X;

    float4 sc0, sh0, sc1, sh1;
    if (applyBn) {
        sc0 = *(const float4*)(g_scale + f0);
        sh0 = *(const float4*)(g_shift + f0);
        sc1 = *(const float4*)(g_scale + f1);
        sh1 = *(const float4*)(g_shift + f1);
    }

    int base = blockIdx.x * AGG_NPB + w * AGG_NPW;
    int nEnd = min(base + AGG_NPW, N);
    for (int n = base; n < nEnd; n++) {
        float d2 = g_dinv2[n];
        const float* rp = S + (size_t)n * K;
        float4 v0 = *(const float4*)(rp + f0);
        float4 v1 = wide ? *(const float4*)(rp + f1) : make_float4(0.f, 0.f, 0.f, 0.f);
        if (applyBn) {
            v0.x = fmaxf(fmaf(v0.x, sc0.x, sh0.x), 0.f);
            v0.y = fmaxf(fmaf(v0.y, sc0.y, sh0.y), 0.f);
            v0.z = fmaxf(fmaf(v0.z, sc0.z, sh0.z), 0.f);
            v0.w = fmaxf(fmaf(v0.w, sc0.w, sh0.w), 0.f);
            v1.x = fmaxf(fmaf(v1.x, sc1.x, sh1.x), 0.f);
            v1.y = fmaxf(fmaf(v1.y, sc1.y, sh1.y), 0.f);
            v1.z = fmaxf(fmaf(v1.z, sc1.z, sh1.z), 0.f);
            v1.w = fmaxf(fmaf(v1.w, sc1.w, sh1.w), 0.f);
        }
        float4 a0, a1;
        a0.x = v0.x * d2; a0.y = v0.y * d2; a0.z = v0.z * d2; a0.w = v0.w * d2;
        a1.x = v1.x * d2; a1.y = v1.y * d2; a1.z = v1.z * d2; a1.w = v1.w * d2;

        int e0 = g_rowptr[n], e1 = g_rowptr[n + 1];
        for (int e = e0; e < e1; e++) {
            int src = g_csrc[e];
            float c = g_ccoef[e];
            const float* sr = S + (size_t)src * K;
            float4 w0 = *(const float4*)(sr + f0);
            float4 w1 = wide ? *(const float4*)(sr + f1) : make_float4(0.f, 0.f, 0.f, 0.f);
            if (applyBn) {
                w0.x = fmaxf(fmaf(w0.x, sc0.x, sh0.x), 0.f);
                w0.y = fmaxf(fmaf(w0.y, sc0.y, sh0.y), 0.f);
                w0.z = fmaxf(fmaf(w0.z, sc0.z, sh0.z), 0.f);
                w0.w = fmaxf(fmaf(w0.w, sc0.w, sh0.w), 0.f);
                w1.x = fmaxf(fmaf(w1.x, sc1.x, sh1.x), 0.f);
                w1.y = fmaxf(fmaf(w1.y, sc1.y, sh1.y), 0.f);
                w1.z = fmaxf(fmaf(w1.z, sc1.z, sh1.z), 0.f);
                w1.w = fmaxf(fmaf(w1.w, sc1.w, sh1.w), 0.f);
            }
            a0.x = fmaf(w0.x, c, a0.x); a0.y = fmaf(w0.y, c, a0.y);
            a0.z = fmaf(w0.z, c, a0.z); a0.w = fmaf(w0.w, c, a0.w);
            a1.x = fmaf(w1.x, c, a1.x); a1.y = fmaf(w1.y, c, a1.y);
            a1.z = fmaf(w1.z, c, a1.z); a1.w = fmaf(w1.w, c, a1.w);
        }
        float* op = g_bufA + (size_t)n * K;
        *(float4*)(op + f0) = a0;
        if (wide) *(float4*)(op + f1) = a1;
    }
}

// ---------------- pipelined HMMA GEMM: h = a@W + bias, fused BN-stats epilogue ----------
#define ASTRIDE 40
#define STG 10240
#define OFF_AH 0
#define OFF_AL (2 * STG)
#define OFF_BH (4 * STG)
#define OFF_BL (6 * STG)
#define GEMM_SMEM (8 * STG)   // 81920

__global__ void __launch_bounds__(256, 2)
gemm_mma_kernel(int layer, int K, int M, const float* __restrict__ bias) {
    extern __shared__ __align__(16) char smem[];
    uint32_t sb = smem_u32(smem);

    int tid = threadIdx.x;
    int warp = tid >> 5, lane = tid & 31;
    int mw = warp & 1;
    int nw = warp >> 1;
    int tileM = blockIdx.x * 128;
    int colBase = blockIdx.y * 128;

    const float* A = g_bufA;
    const __nv_bfloat16* Wth = g_wth + (size_t)layer * HID * HID + (size_t)colBase * K;
    const __nv_bfloat16* Wtl = g_wtl + (size_t)layer * HID * HID + (size_t)colBase * K;

    float acc[4][4][4];
    #pragma unroll
    for (int i = 0; i < 4; i++)
        #pragma unroll
        for (int j = 0; j < 4; j++)
            #pragma unroll
            for (int v = 0; v < 4; v++) acc[i][j][v] = 0.f;

    int nChunks = K >> 5;
    float4 aReg[4];

    auto loadA = [&](int kt) {
        #pragma unroll
        for (int it = 0; it < 4; it++) {
            int idx = tid + it * 256;
            int row = idx >> 3, seg = idx & 7;
            float4 v = make_float4(0.f, 0.f, 0.f, 0.f);
            int gr = tileM + row;
            if (gr < M)
                v = *(const float4*)(A + (size_t)gr * K + kt + seg * 4);
            aReg[it] = v;
        }
    };
    auto storeA = [&](int stage) {
        uint32_t baseH = sb + OFF_AH + stage * STG;
        uint32_t baseL = sb + OFF_AL + stage * STG;
        #pragma unroll
        for (int it = 0; it < 4; it++) {
            int idx = tid + it * 256;
            int row = idx >> 3, seg = idx & 7;
            float4 v = aReg[it];
            __nv_bfloat16 hx = __float2bfloat16(v.x), hy = __float2bfloat16(v.y);
            __nv_bfloat16 hz = __float2bfloat16(v.z), hw = __float2bfloat16(v.w);
            uint32_t off = (uint32_t)(row * 80 + seg * 8);
            uint2 ph = make_uint2(pack_bf2(hx, hy), pack_bf2(hz, hw));
            uint2 pl = make_uint2(
                pack_bf2(__float2bfloat16(v.x - __bfloat162float(hx)),
                         __float2bfloat16(v.y - __bfloat162float(hy))),
                pack_bf2(__float2bfloat16(v.z - __bfloat162float(hz)),
                         __float2bfloat16(v.w - __bfloat162float(hw))));
            asm volatile("st.shared.v2.b32 [%0], {%1,%2};" :: "r"(baseH + off), "r"(ph.x), "r"(ph.y));
            asm volatile("st.shared.v2.b32 [%0], {%1,%2};" :: "r"(baseL + off), "r"(pl.x), "r"(pl.y));
        }
    };
    auto loadB = [&](int kt, int stage) {
        uint32_t baseH = sb + OFF_BH + stage * STG;
        uint32_t baseL = sb + OFF_BL + stage * STG;
        #pragma unroll
        for (int it = 0; it < 2; it++) {
            int idx = tid + it * 256;
            int row = idx >> 2, seg = idx & 3;
            uint32_t off = (uint32_t)(row * 80 + seg * 16);
            size_t go = (size_t)row * K + kt + seg * 8;
            cp16(baseH + off, Wth + go);
            cp16(baseL + off, Wtl + go);
        }
        asm volatile("cp.async.commit_group;");
    };
    auto compute = [&](int stage) {
        uint32_t aH = sb + OFF_AH + stage * STG, aL = sb + OFF_AL + stage * STG;
        uint32_t bH = sb + OFF_BH + stage * STG, bL = sb + OFF_BL + stage * STG;
        #pragma unroll
        for (int ks = 0; ks < 2; ks++) {
            uint32_t bh[4][2], bl[4][2];
            int brow = nw * 32 + (lane & 7);
            int bcol = ks * 32 + ((lane >> 3) & 1) * 16;
            #pragma unroll
            for (int j = 0; j < 4; j++) {
                uint32_t off = (uint32_t)((brow + j * 8) * 80 + bcol);
                ldm_x2(bh[j][0], bh[j][1], bH + off);
                ldm_x2(bl[j][0], bl[j][1], bL + off);
            }
            int arow = mw * 64 + (lane & 15);
            int acol = ks * 32 + (lane >> 4) * 16;
            #pragma unroll
            for (int i = 0; i < 4; i++) {
                uint32_t off = (uint32_t)((arow + i * 16) * 80 + acol);
                uint32_t ah[4], al[4];
                ldm_x4(ah[0], ah[1], ah[2], ah[3], aH + off);
                ldm_x4(al[0], al[1], al[2], al[3], aL + off);
                #pragma unroll
                for (int j = 0; j < 4; j++) {
                    mma_16816(acc[i][j], ah, bh[j]);
                    mma_16816(acc[i][j], ah, bl[j]);
                    mma_16816(acc[i][j], al, bh[j]);
                }
            }
        }
    };

    loadA(0);
    loadB(0, 0);
    storeA(0);
    asm volatile("cp.async.wait_group 0;");
    __syncthreads();

    for (int c = 0; c < nChunks; c++) {
        int cur = c & 1, nxt = cur ^ 1;
        bool hasNext = (c + 1 < nChunks);
        if (hasNext) {
            loadA((c + 1) << 5);
            loadB((c + 1) << 5, nxt);
        }
        compute(cur);
        if (hasNext) {
            storeA(nxt);
            asm volatile("cp.async.wait_group 0;");
        }
        __syncthreads();
    }

    // ---- epilogue: bias, write h, fused per-feature stats ----
    float* sSum = (float*)smem;          // [128]
    float* sSq  = (float*)(smem + 512);  // [128]
    if (tid < 128) { sSum[tid] = 0.f; sSq[tid] = 0.f; }
    __syncthreads();

    int groupRow = lane >> 2;
    int lcol = nw * 32 + (lane & 3) * 2;    // local column 0..127 (even)
    float colSum[4][2] = {};
    float colSq[4][2] = {};
    #pragma unroll
    for (int i = 0; i < 4; i++) {
        int r0 = tileM + mw * 64 + i * 16 + groupRow;
        #pragma unroll
        for (int half = 0; half < 2; half++) {
            int row = r0 + half * 8;
            if (row >= M) continue;
            #pragma unroll
            for (int j = 0; j < 4; j++) {
                int col = colBase + lcol + j * 8;
                float v0 = acc[i][j][half * 2 + 0] + bias[col];
                float v1 = acc[i][j][half * 2 + 1] + bias[col + 1];
                *(float2*)(g_h + (size_t)row * HID + col) = make_float2(v0, v1);
                colSum[j][0] += v0; colSum[j][1] += v1;
                colSq[j][0] = fmaf(v0, v0, colSq[j][0]);
                colSq[j][1] = fmaf(v1, v1, colSq[j][1]);
            }
        }
    }
    #pragma unroll
    for (int j = 0; j < 4; j++) {
        atomicAdd(&sSum[lcol + j * 8],     colSum[j][0]);
        atomicAdd(&sSum[lcol + j * 8 + 1], colSum[j][1]);
        atomicAdd(&sSq[lcol + j * 8],      colSq[j][0]);
        atomicAdd(&sSq[lcol + j * 8 + 1],  colSq[j][1]);
    }
    __syncthreads();
    if (tid < 128) {
        atomicAdd(&g_stats[colBase + tid], sSum[tid]);
        atomicAdd(&g_stats[HID + colBase + tid], sSq[tid]);
    }
}

// bn finalize + reset stats for the next layer (single block, no race)
__global__ void bn_final_kernel(const float* __restrict__ gamma,
                                const float* __restrict__ beta, int N) {
    int f = threadIdx.x;
    float invN = 1.0f / (float)N;
    float mean = g_stats[f] * invN;
    float var  = g_stats[HID + f] * invN - mean * mean;
    float sc = gamma[f] * rsqrtf(var + EPS);
    g_scale[f] = sc;
    g_shift[f] = beta[f] - mean * sc;
    g_stats[f] = 0.0f;
    g_stats[HID + f] = 0.0f;
}

// ---------------- pooling: run-length accumulation + fused BN3 + ReLU ----------------
#define PNPB 64
__global__ void __launch_bounds__(256) pool_kernel(int N) {
    int f = threadIdx.x;
    int n0 = blockIdx.x * PNPB;
    int n1 = min(n0 + PNPB, N);
    if (n0 >= N) return;
    float sc = g_scale[f], sh = g_shift[f];
    float acc = 0.f;
    int curG = g_batch32[n0];
    for (int n = n0; n < n1; n++) {
        int g = g_batch32[n];
        if (g != curG) {
            atomicAdd(&g_pooled[(size_t)curG * HID + f], acc);
            acc = 0.f;
            curG = g;
        }
        float v = g_h[(size_t)n * HID + f];
        acc += fmaxf(fmaf(v, sc, sh), 0.f);
    }
    atomicAdd(&g_pooled[(size_t)curG * HID + f], acc);
}

// ---------------- MLP head fp32 GEMM ----------------
__global__ __launch_bounds__(256) void head_gemm_kernel(
    const float* __restrict__ B, const float* __restrict__ bias, int M, int K) {
    const float* A = (const float*)g_pooled;
    float* C = g_hidden;
    const int Ncols = HID;

    __shared__ float As[16][64];
    __shared__ float Bs[16][64];
    int tid = threadIdx.x;
    int ty = tid >> 4;
    int tx = tid & 15;
    int rowBase = blockIdx.x * 64;
    int colBase = blockIdx.y * 64;

    float acc[4][4] = {};
    int lr = tid >> 2;
    int lc = tid & 3;
    int br = tid >> 4;
    int bc = tid & 15;

    for (int kt = 0; kt < K; kt += 16) {
        float4 av = make_float4(0.f, 0.f, 0.f, 0.f);
        int arow = rowBase + lr;
        if (arow < M)
            av = *(const float4*)(A + (size_t)arow * K + kt + lc * 4);
        As[lc * 4 + 0][lr] = av.x;
        As[lc * 4 + 1][lr] = av.y;
        As[lc * 4 + 2][lr] = av.z;
        As[lc * 4 + 3][lr] = av.w;
        float4 bv = *(const float4*)(B + (size_t)(kt + br) * Ncols + colBase + bc * 4);
        *(float4*)(&Bs[br][bc * 4]) = bv;
        __syncthreads();
        #pragma unroll
        for (int k = 0; k < 16; k++) {
            float ar[4], brv[4];
            #pragma unroll
            for (int i = 0; i < 4; i++) ar[i]  = As[k][ty * 4 + i];
            #pragma unroll
            for (int j = 0; j < 4; j++) brv[j] = Bs[k][tx * 4 + j];
            #pragma unroll
            for (int i = 0; i < 4; i++)
                #pragma unroll
                for (int j = 0; j < 4; j++)
                    acc[i][j] = fmaf(ar[i], brv[j], acc[i][j]);
        }
        __syncthreads();
    }
    #pragma unroll
    for (int i = 0; i < 4; i++) {
        int row = rowBase + ty * 4 + i;
        if (row >= M) continue;
        int col = colBase + tx * 4;
        float4 v;
        float* vp = &v.x;
        #pragma unroll
        for (int j = 0; j < 4; j++) {
            float t = acc[i][j] + bias[col + j];
            vp[j] = fmaxf(t, 0.f);
        }
        *(float4*)(C + (size_t)row * Ncols + col) = v;
    }
}

// ---------------- final dot ----------------
__global__ void final_dot_kernel(const float* __restrict__ LW2,
                                 const float* __restrict__ Lb2,
                                 float* __restrict__ out, int G) {
    int warp = (blockIdx.x * blockDim.x + threadIdx.x) >> 5;
    int lane = threadIdx.x & 31;
    if (warp >= G) return;
    const float* hrow = g_hidden + (size_t)warp * HID;
    float s = 0.f;
    #pragma unroll
    for (int i = 0; i < 8; i++)
        s = fmaf(hrow[lane + 32 * i], LW2[lane + 32 * i], s);
    #pragma unroll
    for (int o = 16; o; o >>= 1) s += __shfl_down_sync(0xffffffffu, s, o);
    if (lane == 0) out[warp] = s + Lb2[0];
}

// ---------------- host: launches ONLY ----------------
extern "C" void kernel_launch(void* const* d_in, const int* in_sizes, int n_in,
                              void* d_out, int out_size) {
    const float* x = (const float*)d_in[0];
    const unsigned int* eiRaw    = (const unsigned int*)d_in[1];
    const unsigned int* batchRaw = (const unsigned int*)d_in[2];
    const float* W1  = (const float*)d_in[3];
    const float* b1  = (const float*)d_in[4];
    const float* W2  = (const float*)d_in[5];
    const float* b2  = (const float*)d_in[6];
    const float* W3  = (const float*)d_in[7];
    const float* b3  = (const float*)d_in[8];
    const float* g1  = (const float*)d_in[9];
    const float* be1 = (const float*)d_in[10];
    const float* g2  = (const float*)d_in[11];
    const float* be2 = (const float*)d_in[12];
    const float* g3  = (const float*)d_in[13];
    const float* be3 = (const float*)d_in[14];
    const float* LW1 = (const float*)d_in[15];
    const float* Lb1 = (const float*)d_in[16];
    const float* LW2 = (const float*)d_in[17];
    const float* Lb2 = (const float*)d_in[18];
    float* out = (float*)d_out;

    const int N = in_sizes[0] / FIN;
    const int E = in_sizes[1] / 2;
    const int G = out_size;

    cudaFuncSetAttribute(gemm_mma_kernel, cudaFuncAttributeMaxDynamicSharedMemorySize, GEMM_SMEM);

    dim3 ggrid((N + 127) / 128, HID / 128);
    int aggGrid = (N + AGG_NPB - 1) / AGG_NPB;

    // prep: index conversion + CSR build
    zero_kernel<<<(N + 255) / 256, 256>>>(0, N);                // degi + anyOdd flag
    det_kernel<<<(E + 255) / 256, 256>>>(eiRaw, 2 * E);
    conv_deg_kernel<<<(E + 255) / 256, 256>>>(eiRaw, batchRaw, E, N);
    dinv_kernel<<<(N + 255) / 256, 256>>>(N);
    scan_kernel<<<1, 1024>>>(N);
    coeff_csr_kernel<<<(E + 255) / 256, 256>>>(E);
    // weight transpose + bf16 split
    wt_kernel<<<(FIN * HID + 255) / 256, 256>>>(W1, 0, FIN);
    wt_kernel<<<(HID * HID + 255) / 256, 256>>>(W2, 1, HID);
    wt_kernel<<<(HID * HID + 255) / 256, 256>>>(W3, 2, HID);
    zero_kernel<<<2, 256>>>(1, 2 * HID);                        // stats

    // layer 1: agg(x) -> gemm(+stats) -> bn_final
    agg_kernel<<<aggGrid, 256>>>(N, FIN, x, 0);
    gemm_mma_kernel<<<ggrid, 256, GEMM_SMEM>>>(0, FIN, N, b1);
    bn_final_kernel<<<1, HID>>>(g1, be1, N);
    // layer 2
    agg_kernel<<<aggGrid, 256>>>(N, HID, nullptr, 1);
    gemm_mma_kernel<<<ggrid, 256, GEMM_SMEM>>>(1, HID, N, b2);
    bn_final_kernel<<<1, HID>>>(g2, be2, N);
    // layer 3
    agg_kernel<<<aggGrid, 256>>>(N, HID, nullptr, 1);
    gemm_mma_kernel<<<ggrid, 256, GEMM_SMEM>>>(2, HID, N, b3);
    bn_final_kernel<<<1, HID>>>(g3, be3, N);

    // global add pool (BN3 + ReLU fused, run-length accumulation)
    zero_kernel<<<(G * HID + 255) / 256, 256>>>(2, G * HID);
    pool_kernel<<<(N + PNPB - 1) / PNPB, 256>>>(N);

    // MLP head
    dim3 mgrid((G + 63) / 64, HID / 64);
    head_gemm_kernel<<<mgrid, 256>>>(LW1, Lb1, G, HID);
    final_dot_kernel<<<(G * 32 + 255) / 256, 256>>>(LW2, Lb2, out, G);
}